// round 10
// baseline (speedup 1.0000x reference)
#include <cuda_runtime.h>
#include <cuda_fp16.h>

#define NPIX  65536
#define HW4K  4096
#define CIN   256
#define KC    32          // fp32 channels per GEMM K-chunk (16 half2 rows)
#define KR2   16          // half2 rows per chunk
#define FINT  128
#define SR2   136         // smem row stride in half2 units (conflict-free)
#define EPC   68          // epilogue smem row stride (half2 units)

// Scratch (device globals — no runtime allocation allowed)
__device__ unsigned d_Ygh[FINT * NPIX / 2];   // Y_g as fp16x2 pairs (16.8 MB)
__device__ unsigned d_Yxh[FINT * NPIX / 2];   // Y_x as fp16x2 pairs
__device__ float d_S[NPIX];
__device__ float d_stats[4 * FINT + 2];  // sum_g, sq_g, sum_x, sq_x, s_sum, s_sq
__device__ unsigned d_Wg2[(CIN / 2) * FINT];  // W_g packed half2 (k-pairs) [c2][o]
__device__ unsigned d_Wx2[(CIN / 2) * FINT];  // W_x packed half2 (k-pairs) [c2][o]

// ---------------------------------------------------------------------------
// helpers
// ---------------------------------------------------------------------------
__device__ __forceinline__ unsigned packh2(float lo, float hi) {
    __half2 h = __floats2half2_rn(lo, hi);
    return *(unsigned*)&h;
}

__device__ __forceinline__ void mma16(float* c,
                                      unsigned a0, unsigned a1, unsigned a2, unsigned a3,
                                      unsigned b0, unsigned b1) {
    asm volatile(
        "mma.sync.aligned.m16n8k16.row.col.f32.f16.f16.f32 "
        "{%0,%1,%2,%3},{%4,%5,%6,%7},{%8,%9},{%0,%1,%2,%3};\n"
        : "+f"(c[0]), "+f"(c[1]), "+f"(c[2]), "+f"(c[3])
        : "r"(a0), "r"(a1), "r"(a2), "r"(a3), "r"(b0), "r"(b1));
}

__device__ __forceinline__ void cpa16(void* dst, const void* src) {
    unsigned d = (unsigned)__cvta_generic_to_shared(dst);
    asm volatile("cp.async.cg.shared.global [%0], [%1], 16;\n" :: "r"(d), "l"(src));
}
__device__ __forceinline__ void cpa_commit() {
    asm volatile("cp.async.commit_group;\n");
}

// ---------------------------------------------------------------------------
// prep: pack both weight matrices into k-pair half2 layout:
//   d_W2[c2 * FINT + o] = half2(W[o][2*c2], W[o][2*c2+1])
// block 0 also zeroes the stats accumulators.
// ---------------------------------------------------------------------------
__global__ void prep_w_kernel(const float* __restrict__ wg,
                              const float* __restrict__ wx)
{
    const int i  = blockIdx.x * 256 + threadIdx.x;   // 0..16383
    const int c2 = i >> 7;
    const int o  = i & 127;
    d_Wg2[c2 * FINT + o] = packh2(wg[o * CIN + 2 * c2], wg[o * CIN + 2 * c2 + 1]);
    d_Wx2[c2 * FINT + o] = packh2(wx[o * CIN + 2 * c2], wx[o * CIN + 2 * c2 + 1]);
    if (blockIdx.x == 0) {
        for (int k = threadIdx.x; k < 4 * FINT + 2; k += 256) d_stats[k] = 0.0f;
    }
}

// ---------------------------------------------------------------------------
// Fused fp16 tensor-core GEMMs (blockIdx.y = path: 0 -> g, 1 -> x).
// Y[o,p] = sum_c W[o,c]*X[b,c,hw] + bias[o]   (fp16 mma.m16n8k16, fp32 accum)
// CTA: 128 channels x 128 pixels, 8 warps, warp tile 32(ch) x 64(px).
// KC=32 chunks, one barrier per chunk (X reg-prefetch, W cp.async).
// Epilogue: bias add, stats from regs, fp16 tile staged in smem (union-aliased
// over mainloop buffers), then fully-coalesced 16B global stores.
// ---------------------------------------------------------------------------
union SmemU {
    struct {
        unsigned Ws2[2][KR2][SR2];
        unsigned Xs2[2][KR2][SR2];
    } mm;                                  // 2*16*136*4*2 = 34816 B
    unsigned ep[FINT][EPC];                // 128*68*4    = 34816 B
};

__global__ __launch_bounds__(256, 2)
void gemm_tc_kernel(const float* __restrict__ G,
                    const float* __restrict__ Xin,
                    const float* __restrict__ bg,
                    const float* __restrict__ bx)
{
    __shared__ __align__(16) SmemU su;

    const int path = blockIdx.y;
    const float*    __restrict__ X    = path ? Xin : G;
    const unsigned* __restrict__ Wt   = path ? d_Wx2 : d_Wg2;
    const float*    __restrict__ bias = path ? bx : bg;
    unsigned* __restrict__ Yh   = path ? d_Yxh : d_Ygh;
    float* __restrict__ ssum = d_stats + path * 256;
    float* __restrict__ ssq  = ssum + FINT;

    const int t    = threadIdx.x;
    const int lane = t & 31;
    const int wid  = t >> 5;            // 0..7
    const int g    = lane >> 2;         // 0..7
    const int tig  = lane & 3;          // 0..3
    const int m0w  = (wid >> 1) * 32;   // 4 m-warps
    const int n0w  = (wid & 1) * 64;    // 2 n-warps

    const int p0  = blockIdx.x * 128;
    const int b   = p0 >> 12;
    const int hw0 = p0 & 4095;
    const float* Xb = X + (size_t)b * (CIN * HW4K) + hw0;

    float acc[2][8][4];
    #pragma unroll
    for (int i = 0; i < 2; i++)
        #pragma unroll
        for (int j = 0; j < 8; j++)
            #pragma unroll
            for (int r = 0; r < 4; r++) acc[i][j][r] = 0.0f;

    // loader mapping: per chunk 16 half2-rows x 128 half2 = 512 uint4;
    // 256 threads -> 2 units each (unit: row ur, 4 half2 at col uc).
    int ur[2], uc[2];
    #pragma unroll
    for (int r = 0; r < 2; r++) {
        int u = t + 256 * r;
        ur[r] = u >> 5;              // half2 row 0..15
        uc[r] = (u & 31) * 4;        // col (pixels for X, o-channels for W)
    }

    // prologue: W chunk0 via cp.async, X chunk0 into regs
    #pragma unroll
    for (int r = 0; r < 2; r++)
        cpa16(&su.mm.Ws2[0][ur[r]][uc[r]], Wt + ur[r] * FINT + uc[r]);
    cpa_commit();

    float4 xlo[2], xhi[2];
    #pragma unroll
    for (int r = 0; r < 2; r++) {
        const float* q = Xb + (size_t)(2 * ur[r]) * HW4K + uc[r];
        xlo[r] = *(const float4*)q;
        xhi[r] = *(const float4*)(q + HW4K);
    }

    const int NCH = CIN / KC;   // 8 chunks
    for (int ch = 0; ch < NCH; ch++) {
        const int buf = ch & 1;
        // store prefetched X (pack to half2)
        #pragma unroll
        for (int r = 0; r < 2; r++) {
            uint4 xp;
            xp.x = packh2(xlo[r].x, xhi[r].x);
            xp.y = packh2(xlo[r].y, xhi[r].y);
            xp.z = packh2(xlo[r].z, xhi[r].z);
            xp.w = packh2(xlo[r].w, xhi[r].w);
            *(uint4*)&su.mm.Xs2[buf][ur[r]][uc[r]] = xp;
        }
        asm volatile("cp.async.wait_group 0;\n");   // W(buf) arrived
        __syncthreads();

        if (ch + 1 < NCH) {   // fills for next chunk target buf^1 (safe post-sync)
            const int c0 = (ch + 1) * KC;
            #pragma unroll
            for (int r = 0; r < 2; r++) {
                const float* q = Xb + (size_t)(c0 + 2 * ur[r]) * HW4K + uc[r];
                xlo[r] = *(const float4*)q;
                xhi[r] = *(const float4*)(q + HW4K);
                cpa16(&su.mm.Ws2[buf ^ 1][ur[r]][uc[r]],
                      Wt + (c0 / 2 + ur[r]) * FINT + uc[r]);
            }
            cpa_commit();
        }

        // compute: 2 k-steps of m16n8k16 over the 16 half2 rows
        #pragma unroll
        for (int ks = 0; ks < 2; ks++) {
            const int kb = 8 * ks;
            unsigned b0[8], b1[8];
            #pragma unroll
            for (int j = 0; j < 8; j++) {
                const int n = n0w + 8 * j + g;
                b0[j] = su.mm.Xs2[buf][kb + tig][n];
                b1[j] = su.mm.Xs2[buf][kb + tig + 4][n];
            }
            #pragma unroll
            for (int i = 0; i < 2; i++) {
                const int m0 = m0w + 16 * i;
                unsigned a0 = su.mm.Ws2[buf][kb + tig][m0 + g];
                unsigned a1 = su.mm.Ws2[buf][kb + tig][m0 + g + 8];
                unsigned a2 = su.mm.Ws2[buf][kb + tig + 4][m0 + g];
                unsigned a3 = su.mm.Ws2[buf][kb + tig + 4][m0 + g + 8];
                #pragma unroll
                for (int j = 0; j < 8; j++)
                    mma16(acc[i][j], a0, a1, a2, a3, b0[j], b1[j]);
            }
        }
    }

    __syncthreads();   // mainloop smem reads done; safe to alias as epilogue tile

    // Epilogue phase 1: bias, stats from regs, fp16 tile into smem
    #pragma unroll
    for (int i = 0; i < 2; i++) {
        const int r0 = m0w + 16 * i + g;
        const int r1 = r0 + 8;
        const float b0v = __ldg(&bias[r0]);
        const float b1v = __ldg(&bias[r1]);
        float s0 = 0.f, q0 = 0.f, s1 = 0.f, q1 = 0.f;
        #pragma unroll
        for (int j = 0; j < 8; j++) {
            float y00 = acc[i][j][0] + b0v, y01 = acc[i][j][1] + b0v;
            float y10 = acc[i][j][2] + b1v, y11 = acc[i][j][3] + b1v;
            const int c2 = (n0w >> 1) + 4 * j + tig;     // half2 column
            su.ep[r0][c2] = packh2(y00, y01);
            su.ep[r1][c2] = packh2(y10, y11);
            s0 += y00 + y01;  q0 += y00 * y00 + y01 * y01;
            s1 += y10 + y11;  q1 += y10 * y10 + y11 * y11;
        }
        #pragma unroll
        for (int m = 1; m <= 2; m <<= 1) {
            s0 += __shfl_xor_sync(0xFFFFFFFFu, s0, m);
            q0 += __shfl_xor_sync(0xFFFFFFFFu, q0, m);
            s1 += __shfl_xor_sync(0xFFFFFFFFu, s1, m);
            q1 += __shfl_xor_sync(0xFFFFFFFFu, q1, m);
        }
        if (tig == 0) {
            atomicAdd(&ssum[r0], s0);
            atomicAdd(&ssq[r0],  q0);
            atomicAdd(&ssum[r1], s1);
            atomicAdd(&ssq[r1],  q1);
        }
    }
    __syncthreads();

    // Epilogue phase 2: coalesced 16B stores (8 uint4 per thread)
    {
        const int rr = t >> 1;                 // channel row 0..127
        const int cb = (t & 1) * 8;            // uint4 index base (row = 16 uint4)
        unsigned* dst = Yh + (size_t)rr * (NPIX / 2) + (p0 >> 1);
        #pragma unroll
        for (int k = 0; k < 8; k++) {
            uint4 v = *(const uint4*)&su.ep[rr][(cb + k) * 4];
            *(uint4*)(dst + (cb + k) * 4) = v;
        }
    }
}

// ---------------------------------------------------------------------------
// psi: inlines BN-coefficient computation, then
// s[p] = sum_o psi_w[o]*relu(ag*yg + ax*yx + cc) + psi_b, plus stats of s.
// 128 threads x 2 px; unroll 16 -> 32 outstanding loads per thread.
// ---------------------------------------------------------------------------
__global__ __launch_bounds__(128)
void psi_kernel(const float* __restrict__ wg_gamma,
                const float* __restrict__ wg_beta,
                const float* __restrict__ wx_gamma,
                const float* __restrict__ wx_beta,
                const float* __restrict__ psi_w,
                const float* __restrict__ psi_b)
{
    __shared__ float ags[FINT], axs[FINT], ccs[FINT], pws[FINT];
    const int t = threadIdx.x;   // 0..127 == FINT
    {
        const float n1 = 1.0f / (float)NPIX;
        float mg = d_stats[t] * n1;
        float vg = d_stats[FINT + t] * n1 - mg * mg;
        float ag = wg_gamma[t] * rsqrtf(vg + 1e-5f);
        float cg = wg_beta[t] - ag * mg;
        float mx = d_stats[2 * FINT + t] * n1;
        float vx = d_stats[3 * FINT + t] * n1 - mx * mx;
        float ax = wx_gamma[t] * rsqrtf(vx + 1e-5f);
        float cx = wx_beta[t] - ax * mx;
        ags[t] = ag;
        axs[t] = ax;
        ccs[t] = cg + cx;
        pws[t] = psi_w[t];
    }
    __syncthreads();

    const int p = (blockIdx.x * 128 + t) * 2;        // grid = NPIX/256
    const size_t ph = (size_t)p >> 1;
    float ax0 = 0.f, ax1 = 0.f;
    #pragma unroll 16
    for (int o = 0; o < FINT; o++) {
        const size_t idx = ((size_t)o * NPIX >> 1) + ph;
        float2 vg = __half22float2(*(const __half2*)&d_Ygh[idx]);
        float2 vx = __half22float2(*(const __half2*)&d_Yxh[idx]);
        const float ag = ags[o], axx = axs[o], cc = ccs[o], pw = pws[o];
        ax0 = fmaf(pw, fmaxf(fmaf(ag, vg.x, fmaf(axx, vx.x, cc)), 0.f), ax0);
        ax1 = fmaf(pw, fmaxf(fmaf(ag, vg.y, fmaf(axx, vx.y, cc)), 0.f), ax1);
    }
    const float pb = psi_b[0];
    ax0 += pb; ax1 += pb;
    *(float2*)&d_S[p] = make_float2(ax0, ax1);

    float s = ax0 + ax1;
    float q = ax0 * ax0 + ax1 * ax1;
    #pragma unroll
    for (int m = 16; m >= 1; m >>= 1) {
        s += __shfl_xor_sync(0xFFFFFFFFu, s, m);
        q += __shfl_xor_sync(0xFFFFFFFFu, q, m);
    }
    __shared__ float ws[4], wq[4];
    const int lane = t & 31, w = t >> 5;
    if (lane == 0) { ws[w] = s; wq[w] = q; }
    __syncthreads();
    if (t == 0) {
        float ts = ws[0] + ws[1] + ws[2] + ws[3];
        float tq = wq[0] + wq[1] + wq[2] + wq[3];
        atomicAdd(&d_stats[4 * FINT + 0], ts);
        atomicAdd(&d_stats[4 * FINT + 1], tq);
    }
}

// ---------------------------------------------------------------------------
// out: inlines final BN affine:
// out[b,c,hw] = x[b,c,hw] * sigmoid(a*s[p] + c)    (fast exp/div, 8 elems/thread)
// ---------------------------------------------------------------------------
__global__ __launch_bounds__(256)
void out_kernel(const float* __restrict__ X, float* __restrict__ O,
                const float* __restrict__ psi_gamma,
                const float* __restrict__ psi_beta)
{
    const float n1 = 1.0f / (float)NPIX;
    const float m = d_stats[4 * FINT + 0] * n1;
    const float v = d_stats[4 * FINT + 1] * n1 - m * m;
    const float a = psi_gamma[0] * rsqrtf(v + 1e-5f);
    const float c = psi_beta[0] - a * m;

    const size_t i = (size_t)blockIdx.x * 256 + threadIdx.x;
    const size_t e = i * 8;
    const int bidx = (int)(e >> 20);       // / (256*4096)
    const int hw   = (int)(e & 4095);
    const int p    = (bidx << 12) + hw;

    float4 xv0 = *(const float4*)(X + e);
    float4 xv1 = *(const float4*)(X + e + 4);
    float4 sv0 = *(const float4*)(d_S + p);
    float4 sv1 = *(const float4*)(d_S + p + 4);
    float4 r0, r1;
    r0.x = __fdividef(xv0.x, 1.0f + __expf(-fmaf(a, sv0.x, c)));
    r0.y = __fdividef(xv0.y, 1.0f + __expf(-fmaf(a, sv0.y, c)));
    r0.z = __fdividef(xv0.z, 1.0f + __expf(-fmaf(a, sv0.z, c)));
    r0.w = __fdividef(xv0.w, 1.0f + __expf(-fmaf(a, sv0.w, c)));
    r1.x = __fdividef(xv1.x, 1.0f + __expf(-fmaf(a, sv1.x, c)));
    r1.y = __fdividef(xv1.y, 1.0f + __expf(-fmaf(a, sv1.y, c)));
    r1.z = __fdividef(xv1.z, 1.0f + __expf(-fmaf(a, sv1.z, c)));
    r1.w = __fdividef(xv1.w, 1.0f + __expf(-fmaf(a, sv1.w, c)));
    *(float4*)(O + e)     = r0;
    *(float4*)(O + e + 4) = r1;
}

// ---------------------------------------------------------------------------
extern "C" void kernel_launch(void* const* d_in, const int* in_sizes, int n_in,
                              void* d_out, int out_size)
{
    const float* g         = (const float*)d_in[0];
    const float* x         = (const float*)d_in[1];
    const float* wg_w      = (const float*)d_in[2];
    const float* wg_b      = (const float*)d_in[3];
    const float* wg_gamma  = (const float*)d_in[4];
    const float* wg_beta   = (const float*)d_in[5];
    const float* wx_w      = (const float*)d_in[6];
    const float* wx_b      = (const float*)d_in[7];
    const float* wx_gamma  = (const float*)d_in[8];
    const float* wx_beta   = (const float*)d_in[9];
    const float* psi_w     = (const float*)d_in[10];
    const float* psi_b     = (const float*)d_in[11];
    const float* psi_gamma = (const float*)d_in[12];
    const float* psi_beta  = (const float*)d_in[13];
    float* out = (float*)d_out;

    prep_w_kernel<<<(CIN / 2 * FINT) / 256, 256>>>(wg_w, wx_w);
    gemm_tc_kernel<<<dim3(NPIX / 128, 2), 256>>>(g, x, wg_b, wx_b);
    psi_kernel<<<NPIX / 256, 128>>>(wg_gamma, wg_beta, wx_gamma, wx_beta,
                                    psi_w, psi_b);
    out_kernel<<<(16 * CIN * HW4K) / (8 * 256), 256>>>(x, out, psi_gamma, psi_beta);
}

// round 11
// speedup vs baseline: 1.3341x; 1.3341x over previous
#include <cuda_runtime.h>
#include <cuda_fp16.h>

#define NPIX  65536
#define HW4K  4096
#define CIN   256
#define KC    32          // fp32 channels per GEMM K-chunk (16 half2 rows)
#define KR2   16          // half2 rows per chunk
#define FINT  128
#define SR2   136         // smem row stride in half2 units (conflict-free)

// Scratch (device globals — no runtime allocation allowed)
__device__ unsigned d_Ygh[FINT * NPIX / 2];   // Y_g as fp16x2 pairs (16.8 MB)
__device__ unsigned d_Yxh[FINT * NPIX / 2];   // Y_x as fp16x2 pairs
__device__ float d_S[NPIX];
__device__ float d_stats[4 * FINT + 2];  // sum_g, sq_g, sum_x, sq_x, s_sum, s_sq
__device__ unsigned d_Wg2[(CIN / 2) * FINT];  // W_g packed half2 (k-pairs) [c2][o]
__device__ unsigned d_Wx2[(CIN / 2) * FINT];  // W_x packed half2 (k-pairs) [c2][o]

// ---------------------------------------------------------------------------
// helpers
// ---------------------------------------------------------------------------
__device__ __forceinline__ unsigned packh2(float lo, float hi) {
    __half2 h = __floats2half2_rn(lo, hi);
    return *(unsigned*)&h;
}

__device__ __forceinline__ void mma16(float* c,
                                      unsigned a0, unsigned a1, unsigned a2, unsigned a3,
                                      unsigned b0, unsigned b1) {
    asm volatile(
        "mma.sync.aligned.m16n8k16.row.col.f32.f16.f16.f32 "
        "{%0,%1,%2,%3},{%4,%5,%6,%7},{%8,%9},{%0,%1,%2,%3};\n"
        : "+f"(c[0]), "+f"(c[1]), "+f"(c[2]), "+f"(c[3])
        : "r"(a0), "r"(a1), "r"(a2), "r"(a3), "r"(b0), "r"(b1));
}

__device__ __forceinline__ void cpa16(void* dst, const void* src) {
    unsigned d = (unsigned)__cvta_generic_to_shared(dst);
    asm volatile("cp.async.cg.shared.global [%0], [%1], 16;\n" :: "r"(d), "l"(src));
}
__device__ __forceinline__ void cpa_commit() {
    asm volatile("cp.async.commit_group;\n");
}

// ---------------------------------------------------------------------------
// prep: pack both weight matrices into k-pair half2 layout:
//   d_W2[c2 * FINT + o] = half2(W[o][2*c2], W[o][2*c2+1])
// block 0 also zeroes the stats accumulators.
// ---------------------------------------------------------------------------
__global__ void prep_w_kernel(const float* __restrict__ wg,
                              const float* __restrict__ wx)
{
    const int i  = blockIdx.x * 256 + threadIdx.x;   // 0..16383
    const int c2 = i >> 7;
    const int o  = i & 127;
    d_Wg2[c2 * FINT + o] = packh2(wg[o * CIN + 2 * c2], wg[o * CIN + 2 * c2 + 1]);
    d_Wx2[c2 * FINT + o] = packh2(wx[o * CIN + 2 * c2], wx[o * CIN + 2 * c2 + 1]);
    if (blockIdx.x == 0) {
        for (int k = threadIdx.x; k < 4 * FINT + 2; k += 256) d_stats[k] = 0.0f;
    }
}

// ---------------------------------------------------------------------------
// Fused fp16 tensor-core GEMMs (blockIdx.y = path: 0 -> g, 1 -> x).
// Y[o,p] = sum_c W[o,c]*X[b,c,hw] + bias[o]   (fp16 mma.m16n8k16, fp32 accum)
// CTA: 128 channels x 128 pixels, 8 warps, warp tile 32(ch) x 64(px).
// KC=32 chunks, ONE barrier per chunk:
//   X register-prefetch (fp32->half2 pack in regs), W via cp.async.
// Epilogue: bias add, fp16x2 store of Y, per-channel fp32 sum/sumsq atomics.
// ---------------------------------------------------------------------------
__global__ __launch_bounds__(256, 2)
void gemm_tc_kernel(const float* __restrict__ G,
                    const float* __restrict__ Xin,
                    const float* __restrict__ bg,
                    const float* __restrict__ bx)
{
    __shared__ __align__(16) unsigned Ws2[2][KR2][SR2];
    __shared__ __align__(16) unsigned Xs2[2][KR2][SR2];

    const int path = blockIdx.y;
    const float*    __restrict__ X    = path ? Xin : G;
    const unsigned* __restrict__ Wt   = path ? d_Wx2 : d_Wg2;
    const float*    __restrict__ bias = path ? bx : bg;
    unsigned* __restrict__ Yh   = path ? d_Yxh : d_Ygh;
    float* __restrict__ ssum = d_stats + path * 256;
    float* __restrict__ ssq  = ssum + FINT;

    const int t    = threadIdx.x;
    const int lane = t & 31;
    const int wid  = t >> 5;            // 0..7
    const int g    = lane >> 2;         // 0..7
    const int tig  = lane & 3;          // 0..3
    const int m0w  = (wid >> 1) * 32;   // 4 m-warps
    const int n0w  = (wid & 1) * 64;    // 2 n-warps

    const int p0  = blockIdx.x * 128;
    const int b   = p0 >> 12;
    const int hw0 = p0 & 4095;
    const float* Xb = X + (size_t)b * (CIN * HW4K) + hw0;

    float acc[2][8][4];
    #pragma unroll
    for (int i = 0; i < 2; i++)
        #pragma unroll
        for (int j = 0; j < 8; j++)
            #pragma unroll
            for (int r = 0; r < 4; r++) acc[i][j][r] = 0.0f;

    // loader mapping: per chunk 16 half2-rows x 128 half2 = 512 uint4;
    // 256 threads -> 2 units each (unit: row ur, 4 half2 at col uc).
    int ur[2], uc[2];
    #pragma unroll
    for (int r = 0; r < 2; r++) {
        int u = t + 256 * r;
        ur[r] = u >> 5;              // half2 row 0..15
        uc[r] = (u & 31) * 4;        // col (pixels for X, o-channels for W)
    }

    // prologue: W chunk0 via cp.async, X chunk0 into regs
    #pragma unroll
    for (int r = 0; r < 2; r++)
        cpa16(&Ws2[0][ur[r]][uc[r]], Wt + ur[r] * FINT + uc[r]);
    cpa_commit();

    float4 xlo[2], xhi[2];
    #pragma unroll
    for (int r = 0; r < 2; r++) {
        const float* q = Xb + (size_t)(2 * ur[r]) * HW4K + uc[r];
        xlo[r] = *(const float4*)q;
        xhi[r] = *(const float4*)(q + HW4K);
    }

    const int NCH = CIN / KC;   // 8 chunks
    for (int ch = 0; ch < NCH; ch++) {
        const int buf = ch & 1;
        // store prefetched X (pack to half2)
        #pragma unroll
        for (int r = 0; r < 2; r++) {
            uint4 xp;
            xp.x = packh2(xlo[r].x, xhi[r].x);
            xp.y = packh2(xlo[r].y, xhi[r].y);
            xp.z = packh2(xlo[r].z, xhi[r].z);
            xp.w = packh2(xlo[r].w, xhi[r].w);
            *(uint4*)&Xs2[buf][ur[r]][uc[r]] = xp;
        }
        asm volatile("cp.async.wait_group 0;\n");   // W(buf) arrived
        __syncthreads();

        if (ch + 1 < NCH) {   // fills for next chunk target buf^1 (safe post-sync)
            const int c0 = (ch + 1) * KC;
            #pragma unroll
            for (int r = 0; r < 2; r++) {
                const float* q = Xb + (size_t)(c0 + 2 * ur[r]) * HW4K + uc[r];
                xlo[r] = *(const float4*)q;
                xhi[r] = *(const float4*)(q + HW4K);
                cpa16(&Ws2[buf ^ 1][ur[r]][uc[r]],
                      Wt + (c0 / 2 + ur[r]) * FINT + uc[r]);
            }
            cpa_commit();
        }

        // compute: 2 k-steps of m16n8k16 over the 16 half2 rows
        #pragma unroll
        for (int ks = 0; ks < 2; ks++) {
            const int kb = 8 * ks;
            unsigned b0[8], b1[8];
            #pragma unroll
            for (int j = 0; j < 8; j++) {
                const int n = n0w + 8 * j + g;
                b0[j] = Xs2[buf][kb + tig][n];
                b1[j] = Xs2[buf][kb + tig + 4][n];
            }
            #pragma unroll
            for (int i = 0; i < 2; i++) {
                const int m0 = m0w + 16 * i;
                unsigned a0 = Ws2[buf][kb + tig][m0 + g];
                unsigned a1 = Ws2[buf][kb + tig][m0 + g + 8];
                unsigned a2 = Ws2[buf][kb + tig + 4][m0 + g];
                unsigned a3 = Ws2[buf][kb + tig + 4][m0 + g + 8];
                #pragma unroll
                for (int j = 0; j < 8; j++)
                    mma16(acc[i][j], a0, a1, a2, a3, b0[j], b1[j]);
            }
        }
    }

    // Epilogue: bias, fp16x2 store of Y, per-channel fp32 stats
    #pragma unroll
    for (int i = 0; i < 2; i++) {
        const int r0 = m0w + 16 * i + g;
        const int r1 = r0 + 8;
        const float b0v = __ldg(&bias[r0]);
        const float b1v = __ldg(&bias[r1]);
        float s0 = 0.f, q0 = 0.f, s1 = 0.f, q1 = 0.f;
        #pragma unroll
        for (int j = 0; j < 8; j++) {
            float y00 = acc[i][j][0] + b0v, y01 = acc[i][j][1] + b0v;
            float y10 = acc[i][j][2] + b1v, y11 = acc[i][j][3] + b1v;
            const int col = p0 + n0w + 8 * j + 2 * tig;   // even
            Yh[((size_t)r0 * NPIX + col) >> 1] = packh2(y00, y01);
            Yh[((size_t)r1 * NPIX + col) >> 1] = packh2(y10, y11);
            s0 += y00 + y01;  q0 += y00 * y00 + y01 * y01;
            s1 += y10 + y11;  q1 += y10 * y10 + y11 * y11;
        }
        #pragma unroll
        for (int m = 1; m <= 2; m <<= 1) {
            s0 += __shfl_xor_sync(0xFFFFFFFFu, s0, m);
            q0 += __shfl_xor_sync(0xFFFFFFFFu, q0, m);
            s1 += __shfl_xor_sync(0xFFFFFFFFu, s1, m);
            q1 += __shfl_xor_sync(0xFFFFFFFFu, q1, m);
        }
        if (tig == 0) {
            atomicAdd(&ssum[r0], s0);
            atomicAdd(&ssq[r0],  q0);
            atomicAdd(&ssum[r1], s1);
            atomicAdd(&ssq[r1],  q1);
        }
    }
}

// ---------------------------------------------------------------------------
// psi: inlines BN-coefficient computation, then
// s[p] = sum_o psi_w[o]*relu(ag*yg + ax*yx + cc) + psi_b, plus stats of s.
// 128 threads x 2 px; unroll 16 (32 outstanding 4B loads per thread).
// ---------------------------------------------------------------------------
__global__ __launch_bounds__(128)
void psi_kernel(const float* __restrict__ wg_gamma,
                const float* __restrict__ wg_beta,
                const float* __restrict__ wx_gamma,
                const float* __restrict__ wx_beta,
                const float* __restrict__ psi_w,
                const float* __restrict__ psi_b)
{
    __shared__ float ags[FINT], axs[FINT], ccs[FINT], pws[FINT];
    const int t = threadIdx.x;   // 0..127 == FINT
    {
        const float n1 = 1.0f / (float)NPIX;
        float mg = d_stats[t] * n1;
        float vg = d_stats[FINT + t] * n1 - mg * mg;
        float ag = wg_gamma[t] * rsqrtf(vg + 1e-5f);
        float cg = wg_beta[t] - ag * mg;
        float mx = d_stats[2 * FINT + t] * n1;
        float vx = d_stats[3 * FINT + t] * n1 - mx * mx;
        float ax = wx_gamma[t] * rsqrtf(vx + 1e-5f);
        float cx = wx_beta[t] - ax * mx;
        ags[t] = ag;
        axs[t] = ax;
        ccs[t] = cg + cx;
        pws[t] = psi_w[t];
    }
    __syncthreads();

    const int p = (blockIdx.x * 128 + t) * 2;        // grid = NPIX/256
    const size_t ph = (size_t)p >> 1;
    float ax0 = 0.f, ax1 = 0.f;
    #pragma unroll 16
    for (int o = 0; o < FINT; o++) {
        const size_t idx = ((size_t)o * NPIX >> 1) + ph;
        float2 vg = __half22float2(*(const __half2*)&d_Ygh[idx]);
        float2 vx = __half22float2(*(const __half2*)&d_Yxh[idx]);
        const float ag = ags[o], axx = axs[o], cc = ccs[o], pw = pws[o];
        ax0 = fmaf(pw, fmaxf(fmaf(ag, vg.x, fmaf(axx, vx.x, cc)), 0.f), ax0);
        ax1 = fmaf(pw, fmaxf(fmaf(ag, vg.y, fmaf(axx, vx.y, cc)), 0.f), ax1);
    }
    const float pb = psi_b[0];
    ax0 += pb; ax1 += pb;
    *(float2*)&d_S[p] = make_float2(ax0, ax1);

    float s = ax0 + ax1;
    float q = ax0 * ax0 + ax1 * ax1;
    #pragma unroll
    for (int m = 16; m >= 1; m >>= 1) {
        s += __shfl_xor_sync(0xFFFFFFFFu, s, m);
        q += __shfl_xor_sync(0xFFFFFFFFu, q, m);
    }
    __shared__ float ws[4], wq[4];
    const int lane = t & 31, w = t >> 5;
    if (lane == 0) { ws[w] = s; wq[w] = q; }
    __syncthreads();
    if (t == 0) {
        float ts = ws[0] + ws[1] + ws[2] + ws[3];
        float tq = wq[0] + wq[1] + wq[2] + wq[3];
        atomicAdd(&d_stats[4 * FINT + 0], ts);
        atomicAdd(&d_stats[4 * FINT + 1], tq);
    }
}

// ---------------------------------------------------------------------------
// out: inlines final BN affine:
// out[b,c,hw] = x[b,c,hw] * sigmoid(a*s[p] + c)    (fast exp/div, 4 elems/thread)
// ---------------------------------------------------------------------------
__global__ __launch_bounds__(256)
void out_kernel(const float* __restrict__ X, float* __restrict__ O,
                const float* __restrict__ psi_gamma,
                const float* __restrict__ psi_beta)
{
    const float n1 = 1.0f / (float)NPIX;
    const float m = d_stats[4 * FINT + 0] * n1;
    const float v = d_stats[4 * FINT + 1] * n1 - m * m;
    const float a = psi_gamma[0] * rsqrtf(v + 1e-5f);
    const float c = psi_beta[0] - a * m;

    const size_t i = (size_t)blockIdx.x * 256 + threadIdx.x;
    const size_t e = i * 4;
    const int bidx = (int)(e >> 20);       // / (256*4096)
    const int hw   = (int)(e & 4095);
    const int p    = (bidx << 12) + hw;

    float4 xv = *(const float4*)(X + e);
    float4 sv = *(const float4*)(d_S + p);
    float4 r;
    r.x = __fdividef(xv.x, 1.0f + __expf(-fmaf(a, sv.x, c)));
    r.y = __fdividef(xv.y, 1.0f + __expf(-fmaf(a, sv.y, c)));
    r.z = __fdividef(xv.z, 1.0f + __expf(-fmaf(a, sv.z, c)));
    r.w = __fdividef(xv.w, 1.0f + __expf(-fmaf(a, sv.w, c)));
    *(float4*)(O + e) = r;
}

// ---------------------------------------------------------------------------
extern "C" void kernel_launch(void* const* d_in, const int* in_sizes, int n_in,
                              void* d_out, int out_size)
{
    const float* g         = (const float*)d_in[0];
    const float* x         = (const float*)d_in[1];
    const float* wg_w      = (const float*)d_in[2];
    const float* wg_b      = (const float*)d_in[3];
    const float* wg_gamma  = (const float*)d_in[4];
    const float* wg_beta   = (const float*)d_in[5];
    const float* wx_w      = (const float*)d_in[6];
    const float* wx_b      = (const float*)d_in[7];
    const float* wx_gamma  = (const float*)d_in[8];
    const float* wx_beta   = (const float*)d_in[9];
    const float* psi_w     = (const float*)d_in[10];
    const float* psi_b     = (const float*)d_in[11];
    const float* psi_gamma = (const float*)d_in[12];
    const float* psi_beta  = (const float*)d_in[13];
    float* out = (float*)d_out;

    prep_w_kernel<<<(CIN / 2 * FINT) / 256, 256>>>(wg_w, wx_w);
    gemm_tc_kernel<<<dim3(NPIX / 128, 2), 256>>>(g, x, wg_b, wx_b);
    psi_kernel<<<NPIX / 256, 128>>>(wg_gamma, wg_beta, wx_gamma, wx_beta,
                                    psi_w, psi_b);
    out_kernel<<<(16 * CIN * HW4K) / (4 * 256), 256>>>(x, out, psi_gamma, psi_beta);
}

// round 14
// speedup vs baseline: 1.3683x; 1.0257x over previous
#include <cuda_runtime.h>
#include <cuda_fp16.h>

#define NPIX  65536
#define HW4K  4096
#define CIN   256
#define KC    32          // fp32 channels per GEMM K-chunk (16 half2 rows)
#define KR2   16          // half2 rows per chunk
#define FINT  128
#define SR2   136         // smem row stride in half2 units (conflict-free)

// Scratch (device globals — no runtime allocation allowed)
__device__ unsigned d_Ygh[FINT * NPIX / 2];   // Y_g as fp16x2 pairs (16.8 MB)
__device__ unsigned d_Yxh[FINT * NPIX / 2];   // Y_x as fp16x2 pairs
__device__ float d_S[NPIX];
__device__ float d_stats[4 * FINT + 2];  // sum_g, sq_g, sum_x, sq_x, s_sum, s_sq
__device__ unsigned d_Wg2[(CIN / 2) * FINT];  // W_g packed half2 (k-pairs) [c2][o]
__device__ unsigned d_Wx2[(CIN / 2) * FINT];  // W_x packed half2 (k-pairs) [c2][o]

// ---------------------------------------------------------------------------
// helpers
// ---------------------------------------------------------------------------
__device__ __forceinline__ unsigned packh2(float lo, float hi) {
    __half2 h = __floats2half2_rn(lo, hi);
    return *(unsigned*)&h;
}

__device__ __forceinline__ void mma16(float* c,
                                      unsigned a0, unsigned a1, unsigned a2, unsigned a3,
                                      unsigned b0, unsigned b1) {
    asm volatile(
        "mma.sync.aligned.m16n8k16.row.col.f32.f16.f16.f32 "
        "{%0,%1,%2,%3},{%4,%5,%6,%7},{%8,%9},{%0,%1,%2,%3};\n"
        : "+f"(c[0]), "+f"(c[1]), "+f"(c[2]), "+f"(c[3])
        : "r"(a0), "r"(a1), "r"(a2), "r"(a3), "r"(b0), "r"(b1));
}

__device__ __forceinline__ void cpa16(void* dst, const void* src) {
    unsigned d = (unsigned)__cvta_generic_to_shared(dst);
    asm volatile("cp.async.cg.shared.global [%0], [%1], 16;\n" :: "r"(d), "l"(src));
}
__device__ __forceinline__ void cpa_commit() {
    asm volatile("cp.async.commit_group;\n");
}

// ---------------------------------------------------------------------------
// prep: pack both weight matrices into k-pair half2 layout:
//   d_W2[c2 * FINT + o] = half2(W[o][2*c2], W[o][2*c2+1])
// block 0 also zeroes the stats accumulators.
// ---------------------------------------------------------------------------
__global__ void prep_w_kernel(const float* __restrict__ wg,
                              const float* __restrict__ wx)
{
    const int i  = blockIdx.x * 256 + threadIdx.x;   // 0..16383
    const int c2 = i >> 7;
    const int o  = i & 127;
    d_Wg2[c2 * FINT + o] = packh2(wg[o * CIN + 2 * c2], wg[o * CIN + 2 * c2 + 1]);
    d_Wx2[c2 * FINT + o] = packh2(wx[o * CIN + 2 * c2], wx[o * CIN + 2 * c2 + 1]);
    if (blockIdx.x == 0) {
        for (int k = threadIdx.x; k < 4 * FINT + 2; k += 256) d_stats[k] = 0.0f;
    }
}

// ---------------------------------------------------------------------------
// Fused fp16 tensor-core GEMMs (blockIdx.y = path: 0 -> g, 1 -> x).
// Y[o,p] = sum_c W[o,c]*X[b,c,hw] + bias[o]   (fp16 mma.m16n8k16, fp32 accum)
// CTA: 128 channels x 128 pixels, 8 warps, warp tile 32(ch) x 64(px).
// KC=32 chunks, ONE barrier per chunk. X prefetch at DISTANCE 2:
//   xpk[]  = packed half2 for chunk ch+1 (STS'd at next iteration top)
//   fl/fh  = raw fp32 for chunk ch+2 (in flight while ch computes)
// so the F2FP pack never waits on DRAM and every LDG has ~2 chunk-times
// of cover. W at distance 1 via cp.async (L2-resident after wave 1).
// Epilogue: bias add, fp16x2 store of Y, per-channel fp32 sum/sumsq atomics.
// ---------------------------------------------------------------------------
__global__ __launch_bounds__(256, 2)
void gemm_tc_kernel(const float* __restrict__ G,
                    const float* __restrict__ Xin,
                    const float* __restrict__ bg,
                    const float* __restrict__ bx)
{
    __shared__ __align__(16) unsigned Ws2[2][KR2][SR2];
    __shared__ __align__(16) unsigned Xs2[2][KR2][SR2];

    const int path = blockIdx.y;
    const float*    __restrict__ X    = path ? Xin : G;
    const unsigned* __restrict__ Wt   = path ? d_Wx2 : d_Wg2;
    const float*    __restrict__ bias = path ? bx : bg;
    unsigned* __restrict__ Yh   = path ? d_Yxh : d_Ygh;
    float* __restrict__ ssum = d_stats + path * 256;
    float* __restrict__ ssq  = ssum + FINT;

    const int t    = threadIdx.x;
    const int lane = t & 31;
    const int wid  = t >> 5;            // 0..7
    const int g    = lane >> 2;         // 0..7
    const int tig  = lane & 3;          // 0..3
    const int m0w  = (wid >> 1) * 32;   // 4 m-warps
    const int n0w  = (wid & 1) * 64;    // 2 n-warps

    const int p0  = blockIdx.x * 128;
    const int b   = p0 >> 12;
    const int hw0 = p0 & 4095;
    const float* Xb = X + (size_t)b * (CIN * HW4K) + hw0;

    float acc[2][8][4];
    #pragma unroll
    for (int i = 0; i < 2; i++)
        #pragma unroll
        for (int j = 0; j < 8; j++)
            #pragma unroll
            for (int r = 0; r < 4; r++) acc[i][j][r] = 0.0f;

    // loader mapping: per chunk 16 half2-rows x 128 half2 = 512 uint4;
    // 256 threads -> 2 units each (unit: row ur, 4 half2 at col uc).
    int ur[2], uc[2];
    #pragma unroll
    for (int r = 0; r < 2; r++) {
        int u = t + 256 * r;
        ur[r] = u >> 5;              // half2 row 0..15
        uc[r] = (u & 31) * 4;        // col (pixels for X, o-channels for W)
    }

    // prologue: W chunk0 via cp.async; X chunk0 -> pack; X chunk1 LDG in flight
    #pragma unroll
    for (int r = 0; r < 2; r++)
        cpa16(&Ws2[0][ur[r]][uc[r]], Wt + ur[r] * FINT + uc[r]);
    cpa_commit();

    float4 fl[2], fh[2];
    uint4  xpk[2];
    #pragma unroll
    for (int r = 0; r < 2; r++) {
        const float* q = Xb + (size_t)(2 * ur[r]) * HW4K + uc[r];
        fl[r] = *(const float4*)q;
        fh[r] = *(const float4*)(q + HW4K);
    }
    #pragma unroll
    for (int r = 0; r < 2; r++) {
        xpk[r].x = packh2(fl[r].x, fh[r].x);
        xpk[r].y = packh2(fl[r].y, fh[r].y);
        xpk[r].z = packh2(fl[r].z, fh[r].z);
        xpk[r].w = packh2(fl[r].w, fh[r].w);
    }
    #pragma unroll
    for (int r = 0; r < 2; r++) {
        const float* q = Xb + (size_t)(KC + 2 * ur[r]) * HW4K + uc[r];
        fl[r] = *(const float4*)q;
        fh[r] = *(const float4*)(q + HW4K);
    }

    const int NCH = CIN / KC;   // 8 chunks
    for (int ch = 0; ch < NCH; ch++) {
        const int buf = ch & 1;
        // STS packed chunk ch
        #pragma unroll
        for (int r = 0; r < 2; r++)
            *(uint4*)&Xs2[buf][ur[r]][uc[r]] = xpk[r];
        asm volatile("cp.async.wait_group 0;\n");   // W(buf) arrived
        __syncthreads();

        if (ch + 1 < NCH) {
            // pack chunk ch+1 (its LDGs were issued a full chunk ago)
            #pragma unroll
            for (int r = 0; r < 2; r++) {
                xpk[r].x = packh2(fl[r].x, fh[r].x);
                xpk[r].y = packh2(fl[r].y, fh[r].y);
                xpk[r].z = packh2(fl[r].z, fh[r].z);
                xpk[r].w = packh2(fl[r].w, fh[r].w);
            }
            // W for chunk ch+1 (buf^1; safe post-sync)
            const int c0 = (ch + 1) * KC;
            #pragma unroll
            for (int r = 0; r < 2; r++)
                cpa16(&Ws2[buf ^ 1][ur[r]][uc[r]],
                      Wt + (c0 / 2 + ur[r]) * FINT + uc[r]);
            cpa_commit();
            // X LDGs for chunk ch+2 (2 chunk-times of cover)
            if (ch + 2 < NCH) {
                const int c2 = (ch + 2) * KC;
                #pragma unroll
                for (int r = 0; r < 2; r++) {
                    const float* q = Xb + (size_t)(c2 + 2 * ur[r]) * HW4K + uc[r];
                    fl[r] = *(const float4*)q;
                    fh[r] = *(const float4*)(q + HW4K);
                }
            }
        }

        // compute: 2 k-steps of m16n8k16 over the 16 half2 rows
        #pragma unroll
        for (int ks = 0; ks < 2; ks++) {
            const int kb = 8 * ks;
            unsigned b0[8], b1[8];
            #pragma unroll
            for (int j = 0; j < 8; j++) {
                const int n = n0w + 8 * j + g;
                b0[j] = Xs2[buf][kb + tig][n];
                b1[j] = Xs2[buf][kb + tig + 4][n];
            }
            #pragma unroll
            for (int i = 0; i < 2; i++) {
                const int m0 = m0w + 16 * i;
                unsigned a0 = Ws2[buf][kb + tig][m0 + g];
                unsigned a1 = Ws2[buf][kb + tig][m0 + g + 8];
                unsigned a2 = Ws2[buf][kb + tig + 4][m0 + g];
                unsigned a3 = Ws2[buf][kb + tig + 4][m0 + g + 8];
                #pragma unroll
                for (int j = 0; j < 8; j++)
                    mma16(acc[i][j], a0, a1, a2, a3, b0[j], b1[j]);
            }
        }
    }

    // Epilogue: bias, fp16x2 store of Y, per-channel fp32 stats
    #pragma unroll
    for (int i = 0; i < 2; i++) {
        const int r0 = m0w + 16 * i + g;
        const int r1 = r0 + 8;
        const float b0v = __ldg(&bias[r0]);
        const float b1v = __ldg(&bias[r1]);
        float s0 = 0.f, q0 = 0.f, s1 = 0.f, q1 = 0.f;
        #pragma unroll
        for (int j = 0; j < 8; j++) {
            float y00 = acc[i][j][0] + b0v, y01 = acc[i][j][1] + b0v;
            float y10 = acc[i][j][2] + b1v, y11 = acc[i][j][3] + b1v;
            const int col = p0 + n0w + 8 * j + 2 * tig;   // even
            Yh[((size_t)r0 * NPIX + col) >> 1] = packh2(y00, y01);
            Yh[((size_t)r1 * NPIX + col) >> 1] = packh2(y10, y11);
            s0 += y00 + y01;  q0 += y00 * y00 + y01 * y01;
            s1 += y10 + y11;  q1 += y10 * y10 + y11 * y11;
        }
        #pragma unroll
        for (int m = 1; m <= 2; m <<= 1) {
            s0 += __shfl_xor_sync(0xFFFFFFFFu, s0, m);
            q0 += __shfl_xor_sync(0xFFFFFFFFu, q0, m);
            s1 += __shfl_xor_sync(0xFFFFFFFFu, s1, m);
            q1 += __shfl_xor_sync(0xFFFFFFFFu, q1, m);
        }
        if (tig == 0) {
            atomicAdd(&ssum[r0], s0);
            atomicAdd(&ssq[r0],  q0);
            atomicAdd(&ssum[r1], s1);
            atomicAdd(&ssq[r1],  q1);
        }
    }
}

// ---------------------------------------------------------------------------
// psi: inlines BN-coefficient computation, then
// s[p] = sum_o psi_w[o]*relu(ag*yg + ax*yx + cc) + psi_b, plus stats of s.
// 128 threads x 2 px; unroll 16 (32 outstanding 4B loads per thread).
// ---------------------------------------------------------------------------
__global__ __launch_bounds__(128)
void psi_kernel(const float* __restrict__ wg_gamma,
                const float* __restrict__ wg_beta,
                const float* __restrict__ wx_gamma,
                const float* __restrict__ wx_beta,
                const float* __restrict__ psi_w,
                const float* __restrict__ psi_b)
{
    __shared__ float ags[FINT], axs[FINT], ccs[FINT], pws[FINT];
    const int t = threadIdx.x;   // 0..127 == FINT
    {
        const float n1 = 1.0f / (float)NPIX;
        float mg = d_stats[t] * n1;
        float vg = d_stats[FINT + t] * n1 - mg * mg;
        float ag = wg_gamma[t] * rsqrtf(vg + 1e-5f);
        float cg = wg_beta[t] - ag * mg;
        float mx = d_stats[2 * FINT + t] * n1;
        float vx = d_stats[3 * FINT + t] * n1 - mx * mx;
        float ax = wx_gamma[t] * rsqrtf(vx + 1e-5f);
        float cx = wx_beta[t] - ax * mx;
        ags[t] = ag;
        axs[t] = ax;
        ccs[t] = cg + cx;
        pws[t] = psi_w[t];
    }
    __syncthreads();

    const int p = (blockIdx.x * 128 + t) * 2;        // grid = NPIX/256
    const size_t ph = (size_t)p >> 1;
    float ax0 = 0.f, ax1 = 0.f;
    #pragma unroll 16
    for (int o = 0; o < FINT; o++) {
        const size_t idx = ((size_t)o * NPIX >> 1) + ph;
        float2 vg = __half22float2(*(const __half2*)&d_Ygh[idx]);
        float2 vx = __half22float2(*(const __half2*)&d_Yxh[idx]);
        const float ag = ags[o], axx = axs[o], cc = ccs[o], pw = pws[o];
        ax0 = fmaf(pw, fmaxf(fmaf(ag, vg.x, fmaf(axx, vx.x, cc)), 0.f), ax0);
        ax1 = fmaf(pw, fmaxf(fmaf(ag, vg.y, fmaf(axx, vx.y, cc)), 0.f), ax1);
    }
    const float pb = psi_b[0];
    ax0 += pb; ax1 += pb;
    *(float2*)&d_S[p] = make_float2(ax0, ax1);

    float s = ax0 + ax1;
    float q = ax0 * ax0 + ax1 * ax1;
    #pragma unroll
    for (int m = 16; m >= 1; m >>= 1) {
        s += __shfl_xor_sync(0xFFFFFFFFu, s, m);
        q += __shfl_xor_sync(0xFFFFFFFFu, q, m);
    }
    __shared__ float ws[4], wq[4];
    const int lane = t & 31, w = t >> 5;
    if (lane == 0) { ws[w] = s; wq[w] = q; }
    __syncthreads();
    if (t == 0) {
        atomicAdd(&d_stats[4 * FINT + 0], ws[0] + ws[1] + ws[2] + ws[3]);
        atomicAdd(&d_stats[4 * FINT + 1], wq[0] + wq[1] + wq[2] + wq[3]);
    }
}

// ---------------------------------------------------------------------------
// out: inlines final BN affine:
// out[b,c,hw] = x[b,c,hw] * sigmoid(a*s[p] + c)    (fast exp/div, 4 elems/thread)
// ---------------------------------------------------------------------------
__global__ __launch_bounds__(256)
void out_kernel(const float* __restrict__ X, float* __restrict__ O,
                const float* __restrict__ psi_gamma,
                const float* __restrict__ psi_beta)
{
    const float n1 = 1.0f / (float)NPIX;
    const float m = d_stats[4 * FINT + 0] * n1;
    const float v = d_stats[4 * FINT + 1] * n1 - m * m;
    const float a = psi_gamma[0] * rsqrtf(v + 1e-5f);
    const float c = psi_beta[0] - a * m;

    const size_t i = (size_t)blockIdx.x * 256 + threadIdx.x;
    const size_t e = i * 4;
    const int bidx = (int)(e >> 20);       // / (256*4096)
    const int hw   = (int)(e & 4095);
    const int p    = (bidx << 12) + hw;

    float4 xv = *(const float4*)(X + e);
    float4 sv = *(const float4*)(d_S + p);
    float4 r;
    r.x = __fdividef(xv.x, 1.0f + __expf(-fmaf(a, sv.x, c)));
    r.y = __fdividef(xv.y, 1.0f + __expf(-fmaf(a, sv.y, c)));
    r.z = __fdividef(xv.z, 1.0f + __expf(-fmaf(a, sv.z, c)));
    r.w = __fdividef(xv.w, 1.0f + __expf(-fmaf(a, sv.w, c)));
    *(float4*)(O + e) = r;
}

// ---------------------------------------------------------------------------
extern "C" void kernel_launch(void* const* d_in, const int* in_sizes, int n_in,
                              void* d_out, int out_size)
{
    const float* g         = (const float*)d_in[0];
    const float* x         = (const float*)d_in[1];
    const float* wg_w      = (const float*)d_in[2];
    const float* wg_b      = (const float*)d_in[3];
    const float* wg_gamma  = (const float*)d_in[4];
    const float* wg_beta   = (const float*)d_in[5];
    const float* wx_w      = (const float*)d_in[6];
    const float* wx_b      = (const float*)d_in[7];
    const float* wx_gamma  = (const float*)d_in[8];
    const float* wx_beta   = (const float*)d_in[9];
    const float* psi_w     = (const float*)d_in[10];
    const float* psi_b     = (const float*)d_in[11];
    const float* psi_gamma = (const float*)d_in[12];
    const float* psi_beta  = (const float*)d_in[13];
    float* out = (float*)d_out;

    prep_w_kernel<<<(CIN / 2 * FINT) / 256, 256>>>(wg_w, wx_w);
    gemm_tc_kernel<<<dim3(NPIX / 128, 2), 256>>>(g, x, wg_b, wx_b);
    psi_kernel<<<NPIX / 256, 128>>>(wg_gamma, wg_beta, wx_gamma, wx_beta,
                                    psi_w, psi_b);
    out_kernel<<<(16 * CIN * HW4K) / (4 * 256), 256>>>(x, out, psi_gamma, psi_beta);
}